// round 3
// baseline (speedup 1.0000x reference)
#include <cuda_runtime.h>
#include <cuda_bf16.h>
#include <cstdint>

#define D4 32               // float4 per full row (D=128)
#define QPC 4               // float4-quads per CTA (16 columns)
#define THREADS 1024
#define RB (THREADS / QPC)  // 256 distinct row-bases
#define RITER 4             // covers up to 1024 rows per graph
#define MAXROWS 1024
#define NWARP (THREADS / 32)

__device__ __forceinline__ void cp_async16(uint32_t smem_addr, const void* gmem) {
    asm volatile("cp.async.cg.shared.global [%0], [%1], 16;\n"
                 :: "r"(smem_addr), "l"(gmem) : "memory");
}

__global__ __launch_bounds__(THREADS, 2)
void graphnorm_async(const float* __restrict__ x,
                     const float* __restrict__ gamma,
                     const float* __restrict__ beta,
                     const int* __restrict__ batch,
                     float* __restrict__ out)
{
    extern __shared__ float4 tile[];                 // [MAXROWS][QPC] = 64 KB
    __shared__ float4 psum[NWARP][QPC];
    __shared__ float4 psq [NWARP][QPC];
    __shared__ float4 smean[QPC], sinv[QPC];

    const int g    = blockIdx.x;
    const int cb   = blockIdx.y;                     // column block 0..7
    const int quad = threadIdx.x & (QPC - 1);        // 0..3
    const int rb   = threadIdx.x >> 2;               // 0..255
    const int warp = threadIdx.x >> 5;
    const int lane = threadIdx.x & 31;

    const int start = batch[g];
    const int end   = batch[g + 1];
    const int cnt   = end - start;
    const float fcnt = (float)cnt;

    const float4* __restrict__ xv = (const float4*)x;
    float4* __restrict__ ov = (float4*)out;
    const long colq = (long)cb * QPC + quad;         // float4 column index 0..31

    // ---- async load: gmem -> smem tile, no register staging ----
    uint32_t tbase = (uint32_t)__cvta_generic_to_shared(tile);
    #pragma unroll
    for (int i = 0; i < RITER; i++) {
        int r = rb + i * RB;
        if (r < cnt) {
            cp_async16(tbase + (uint32_t)(r * QPC + quad) * 16u,
                       &xv[(long)(start + r) * D4 + colq]);
        }
    }
    asm volatile("cp.async.commit_group;\n" ::: "memory");
    asm volatile("cp.async.wait_group 0;\n" ::: "memory");
    __syncthreads();

    // ---- accumulate sums from smem ----
    float4 s = make_float4(0.f, 0.f, 0.f, 0.f);
    float4 q = make_float4(0.f, 0.f, 0.f, 0.f);
    #pragma unroll
    for (int i = 0; i < RITER; i++) {
        int r = rb + i * RB;
        if (r < cnt) {
            float4 v = tile[r * QPC + quad];
            s.x += v.x; s.y += v.y; s.z += v.z; s.w += v.w;
            q.x += v.x * v.x; q.y += v.y * v.y; q.z += v.z * v.z; q.w += v.w * v.w;
        }
    }

    // ---- warp reduce: lanes {quad, quad+4, ..., quad+28} share a column quad ----
    #pragma unroll
    for (int off = 4; off <= 16; off <<= 1) {
        s.x += __shfl_xor_sync(0xffffffffu, s.x, off);
        s.y += __shfl_xor_sync(0xffffffffu, s.y, off);
        s.z += __shfl_xor_sync(0xffffffffu, s.z, off);
        s.w += __shfl_xor_sync(0xffffffffu, s.w, off);
        q.x += __shfl_xor_sync(0xffffffffu, q.x, off);
        q.y += __shfl_xor_sync(0xffffffffu, q.y, off);
        q.z += __shfl_xor_sync(0xffffffffu, q.z, off);
        q.w += __shfl_xor_sync(0xffffffffu, q.w, off);
    }
    if (lane < QPC) { psum[warp][quad] = s; psq[warp][quad] = q; }
    __syncthreads();

    // ---- final reduce across 32 warps + stats (QPC threads) ----
    if (threadIdx.x < QPC) {
        float4 ts = make_float4(0.f, 0.f, 0.f, 0.f);
        float4 tq = make_float4(0.f, 0.f, 0.f, 0.f);
        #pragma unroll
        for (int w = 0; w < NWARP; w++) {
            float4 a = psum[w][threadIdx.x];
            float4 b = psq [w][threadIdx.x];
            ts.x += a.x; ts.y += a.y; ts.z += a.z; ts.w += a.w;
            tq.x += b.x; tq.y += b.y; tq.z += b.z; tq.w += b.w;
        }
        float4 m, iv;
        m.x = ts.x / fcnt; m.y = ts.y / fcnt; m.z = ts.z / fcnt; m.w = ts.w / fcnt;
        float denom = fcnt - 1.0f;
        iv.x = 1.0f / (sqrtf(fmaxf((tq.x - fcnt * m.x * m.x) / denom, 0.f)) + 1e-5f);
        iv.y = 1.0f / (sqrtf(fmaxf((tq.y - fcnt * m.y * m.y) / denom, 0.f)) + 1e-5f);
        iv.z = 1.0f / (sqrtf(fmaxf((tq.z - fcnt * m.z * m.z) / denom, 0.f)) + 1e-5f);
        iv.w = 1.0f / (sqrtf(fmaxf((tq.w - fcnt * m.w * m.w) / denom, 0.f)) + 1e-5f);
        smean[threadIdx.x] = m;
        sinv [threadIdx.x] = iv;
    }
    __syncthreads();

    // ---- normalize from smem, write out ----
    const float4 g4 = ((const float4*)gamma)[colq];
    const float4 b4 = ((const float4*)beta)[colq];
    const float4 m  = smean[quad];
    const float4 iv = sinv [quad];

    #pragma unroll
    for (int i = 0; i < RITER; i++) {
        int r = rb + i * RB;
        if (r < cnt) {
            float4 v = tile[r * QPC + quad];
            float4 o;
            o.x = g4.x * (v.x - m.x) * iv.x + b4.x;
            o.y = g4.y * (v.y - m.y) * iv.y + b4.y;
            o.z = g4.z * (v.z - m.z) * iv.z + b4.z;
            o.w = g4.w * (v.w - m.w) * iv.w + b4.w;
            ov[(long)(start + r) * D4 + colq] = o;
        }
    }
}

extern "C" void kernel_launch(void* const* d_in, const int* in_sizes, int n_in,
                              void* d_out, int out_size)
{
    const float* x     = (const float*)d_in[0];
    const float* gamma = (const float*)d_in[1];
    const float* beta  = (const float*)d_in[2];
    const int*   batch = (const int*)d_in[3];
    float* out = (float*)d_out;

    const int G = in_sizes[3] - 1;
    const size_t smem = (size_t)MAXROWS * QPC * sizeof(float4);   // 64 KB

    cudaFuncSetAttribute(graphnorm_async,
                         cudaFuncAttributeMaxDynamicSharedMemorySize, (int)smem);

    dim3 grid(G, D4 / QPC);
    graphnorm_async<<<grid, THREADS, smem>>>(x, gamma, beta, batch, out);
}

// round 4
// speedup vs baseline: 1.1488x; 1.1488x over previous
#include <cuda_runtime.h>
#include <cuda_bf16.h>
#include <cooperative_groups.h>
#include <cstdint>

namespace cg = cooperative_groups;

#define D4 32               // float4 per full row (D=128)
#define QPC 8               // float4-quads per CTA (32 columns = 128B/row)
#define THREADS 1024
#define RB (THREADS / QPC)  // 128 distinct row-bases
#define ROWS_PER_CTA 512
#define RITER (ROWS_PER_CTA / RB)   // 4
#define NWARP (THREADS / 32)

__device__ __forceinline__ void cp_async16(uint32_t smem_addr, const void* gmem) {
    asm volatile("cp.async.cg.shared.global [%0], [%1], 16;\n"
                 :: "r"(smem_addr), "l"(gmem) : "memory");
}

__global__ __launch_bounds__(THREADS, 2) __cluster_dims__(2, 1, 1)
void graphnorm_cluster(const float* __restrict__ x,
                       const float* __restrict__ gamma,
                       const float* __restrict__ beta,
                       const int* __restrict__ batch,
                       float* __restrict__ out)
{
    extern __shared__ float4 tile[];                 // [ROWS_PER_CTA][QPC] = 64 KB
    __shared__ float4 psum[NWARP][QPC];
    __shared__ float4 psq [NWARP][QPC];
    __shared__ float4 cpart_sum[QPC];                // CTA partial (DSMEM-exchanged)
    __shared__ float4 cpart_sq [QPC];
    __shared__ float4 smean[QPC], sinv[QPC];

    const int rk   = blockIdx.x;                     // cluster rank: row half 0/1
    const int g    = blockIdx.y;
    const int cb   = blockIdx.z;                     // column block 0..3
    const int quad = threadIdx.x & (QPC - 1);        // 0..7
    const int rb   = threadIdx.x >> 3;               // 0..127
    const int warp = threadIdx.x >> 5;
    const int lane = threadIdx.x & 31;

    const int start = batch[g];
    const int end   = batch[g + 1];
    const int cnt   = end - start;
    const float fcnt = (float)cnt;
    const int h       = cnt >> 1;
    const int myStart = start + rk * h;
    const int myCnt   = rk ? (cnt - h) : h;

    const float4* __restrict__ xv = (const float4*)x;
    float4* __restrict__ ov = (float4*)out;
    const long colq = (long)cb * QPC + quad;         // float4 col 0..31

    // ---- async load: gmem -> smem tile (128B contiguous per row per CTA) ----
    uint32_t tbase = (uint32_t)__cvta_generic_to_shared(tile);
    #pragma unroll
    for (int i = 0; i < RITER; i++) {
        int r = rb + i * RB;
        if (r < myCnt) {
            cp_async16(tbase + (uint32_t)(r * QPC + quad) * 16u,
                       &xv[(long)(myStart + r) * D4 + colq]);
        }
    }
    asm volatile("cp.async.commit_group;\n" ::: "memory");
    asm volatile("cp.async.wait_group 0;\n" ::: "memory");
    __syncthreads();

    // ---- accumulate partial sums from smem ----
    float4 s = make_float4(0.f, 0.f, 0.f, 0.f);
    float4 q = make_float4(0.f, 0.f, 0.f, 0.f);
    #pragma unroll
    for (int i = 0; i < RITER; i++) {
        int r = rb + i * RB;
        if (r < myCnt) {
            float4 v = tile[r * QPC + quad];
            s.x += v.x; s.y += v.y; s.z += v.z; s.w += v.w;
            q.x += v.x * v.x; q.y += v.y * v.y; q.z += v.z * v.z; q.w += v.w * v.w;
        }
    }

    // ---- warp reduce: lanes {quad, quad+8, quad+16, quad+24} share a column ----
    #pragma unroll
    for (int off = 8; off <= 16; off <<= 1) {
        s.x += __shfl_xor_sync(0xffffffffu, s.x, off);
        s.y += __shfl_xor_sync(0xffffffffu, s.y, off);
        s.z += __shfl_xor_sync(0xffffffffu, s.z, off);
        s.w += __shfl_xor_sync(0xffffffffu, s.w, off);
        q.x += __shfl_xor_sync(0xffffffffu, q.x, off);
        q.y += __shfl_xor_sync(0xffffffffu, q.y, off);
        q.z += __shfl_xor_sync(0xffffffffu, q.z, off);
        q.w += __shfl_xor_sync(0xffffffffu, q.w, off);
    }
    if (lane < QPC) { psum[warp][quad] = s; psq[warp][quad] = q; }
    __syncthreads();

    // ---- CTA reduce across 32 warps -> cpart ----
    if (threadIdx.x < QPC) {
        float4 ts = make_float4(0.f, 0.f, 0.f, 0.f);
        float4 tq = make_float4(0.f, 0.f, 0.f, 0.f);
        #pragma unroll
        for (int w = 0; w < NWARP; w++) {
            float4 a = psum[w][threadIdx.x];
            float4 b = psq [w][threadIdx.x];
            ts.x += a.x; ts.y += a.y; ts.z += a.z; ts.w += a.w;
            tq.x += b.x; tq.y += b.y; tq.z += b.z; tq.w += b.w;
        }
        cpart_sum[threadIdx.x] = ts;
        cpart_sq [threadIdx.x] = tq;
    }

    // ---- cluster exchange of partials ----
    cg::cluster_group cluster = cg::this_cluster();
    cluster.sync();

    if (threadIdx.x < QPC) {
        const unsigned peer = rk ^ 1u;
        const float4* peer_sum = cluster.map_shared_rank(cpart_sum, peer);
        const float4* peer_sq  = cluster.map_shared_rank(cpart_sq,  peer);
        float4 ts = cpart_sum[threadIdx.x];
        float4 tq = cpart_sq [threadIdx.x];
        float4 a = peer_sum[threadIdx.x];
        float4 b = peer_sq [threadIdx.x];
        ts.x += a.x; ts.y += a.y; ts.z += a.z; ts.w += a.w;
        tq.x += b.x; tq.y += b.y; tq.z += b.z; tq.w += b.w;

        float4 m, iv;
        m.x = ts.x / fcnt; m.y = ts.y / fcnt; m.z = ts.z / fcnt; m.w = ts.w / fcnt;
        float denom = fcnt - 1.0f;
        iv.x = 1.0f / (sqrtf(fmaxf((tq.x - fcnt * m.x * m.x) / denom, 0.f)) + 1e-5f);
        iv.y = 1.0f / (sqrtf(fmaxf((tq.y - fcnt * m.y * m.y) / denom, 0.f)) + 1e-5f);
        iv.z = 1.0f / (sqrtf(fmaxf((tq.z - fcnt * m.z * m.z) / denom, 0.f)) + 1e-5f);
        iv.w = 1.0f / (sqrtf(fmaxf((tq.w - fcnt * m.w * m.w) / denom, 0.f)) + 1e-5f);
        smean[threadIdx.x] = m;
        sinv [threadIdx.x] = iv;
    }
    __syncthreads();

    // ---- normalize from smem tile, write out ----
    const float4 g4 = ((const float4*)gamma)[colq];
    const float4 b4 = ((const float4*)beta)[colq];
    const float4 m  = smean[quad];
    const float4 iv = sinv [quad];

    #pragma unroll
    for (int i = 0; i < RITER; i++) {
        int r = rb + i * RB;
        if (r < myCnt) {
            float4 v = tile[r * QPC + quad];
            float4 o;
            o.x = g4.x * (v.x - m.x) * iv.x + b4.x;
            o.y = g4.y * (v.y - m.y) * iv.y + b4.y;
            o.z = g4.z * (v.z - m.z) * iv.z + b4.z;
            o.w = g4.w * (v.w - m.w) * iv.w + b4.w;
            ov[(long)(myStart + r) * D4 + colq] = o;
        }
    }

    // keep peer smem alive until both CTAs have read partials (reads happened
    // before normalize; this final sync also satisfies DSMEM lifetime rules)
    cluster.sync();
}

extern "C" void kernel_launch(void* const* d_in, const int* in_sizes, int n_in,
                              void* d_out, int out_size)
{
    const float* x     = (const float*)d_in[0];
    const float* gamma = (const float*)d_in[1];
    const float* beta  = (const float*)d_in[2];
    const int*   batch = (const int*)d_in[3];
    float* out = (float*)d_out;

    const int G = in_sizes[3] - 1;
    const size_t smem = (size_t)ROWS_PER_CTA * QPC * sizeof(float4);   // 64 KB

    cudaFuncSetAttribute(graphnorm_cluster,
                         cudaFuncAttributeMaxDynamicSharedMemorySize, (int)smem);

    dim3 grid(2, G, D4 / QPC);   // (row-half, graph, column-block)
    graphnorm_cluster<<<grid, THREADS, smem>>>(x, gamma, beta, batch, out);
}